// round 16
// baseline (speedup 1.0000x reference)
#include <cuda_runtime.h>
#include <cuda_fp16.h>
#include <math.h>
#include <stdint.h>

#define NN 50000
#define EE 150000
#define RR 3
#define LL 2
#define HH 512
#define NHEADS 8
#define DHH 64
#define NCLSS 23
#define NNHH ((size_t)NN * HH)
#define NCH 49  // ceil(NN/1024)

// ---------------- scratch (device globals; no allocs allowed) ----------------
__device__ __half g_h16[NNHH];
__device__ __half g_go16[(size_t)9 * NNHH];
__device__ __half g_stk16[(size_t)NN * RR * HH];
__device__ __half g_q[(size_t)NN * RR * HH];
__device__ __half g_k[(size_t)NN * RR * HH];
__device__ __half g_v[(size_t)NN * RR * HH];
__device__ __half g_w16[(size_t)24 * HH * HH];  // TRANSPOSED [N][K] f16 weights
__device__ float g_rdo[(size_t)RR * NN];
__device__ float g_rdi[(size_t)RR * NN];
__device__ float g_el[(size_t)RR * NN * NHEADS];
__device__ float g_er[(size_t)RR * NN * NHEADS];
// CSR (dst-indexed) per relation
__device__ int g_cnt[(size_t)RR * NN];
__device__ int g_cur[(size_t)RR * NN];
__device__ int g_off[(size_t)RR * (NN + 1)];
__device__ int g_eid[(size_t)RR * EE];
__device__ int g_psum[RR * 64];

// ---------------- helpers ----------------
__device__ __forceinline__ float block_reduce_sum_128(float val) {
    __shared__ float sh[32];
    __syncthreads();
    int lane = threadIdx.x & 31;
    int wid = threadIdx.x >> 5;
#pragma unroll
    for (int o = 16; o > 0; o >>= 1) val += __shfl_xor_sync(0xffffffffu, val, o);
    if (lane == 0) sh[wid] = val;
    __syncthreads();
    if (wid == 0) {
        float v = (lane < (blockDim.x >> 5)) ? sh[lane] : 0.0f;
#pragma unroll
        for (int o = 16; o > 0; o >>= 1) v += __shfl_xor_sync(0xffffffffu, v, o);
        if (lane == 0) sh[0] = v;
    }
    __syncthreads();
    return sh[0];
}

__device__ __forceinline__ void mma_f16(float* d, const unsigned* a, const unsigned* b) {
    asm volatile(
        "mma.sync.aligned.m16n8k16.row.col.f32.f16.f16.f32 "
        "{%0,%1,%2,%3}, {%4,%5,%6,%7}, {%8,%9}, {%0,%1,%2,%3};"
        : "+f"(d[0]), "+f"(d[1]), "+f"(d[2]), "+f"(d[3])
        : "r"(a[0]), "r"(a[1]), "r"(a[2]), "r"(a[3]), "r"(b[0]), "r"(b[1]));
}

__device__ __forceinline__ void ldsm_x4(unsigned addr, unsigned& r0, unsigned& r1,
                                        unsigned& r2, unsigned& r3) {
    asm volatile(
        "ldmatrix.sync.aligned.m8n8.x4.shared.b16 {%0,%1,%2,%3}, [%4];"
        : "=r"(r0), "=r"(r1), "=r"(r2), "=r"(r3)
        : "r"(addr));
}

__device__ __forceinline__ void cp16(void* smem_dst, const void* gmem_src, bool pred) {
    unsigned saddr = (unsigned)__cvta_generic_to_shared(smem_dst);
    int sz = pred ? 16 : 0;
    asm volatile("cp.async.cg.shared.global [%0], [%1], 16, %2;\n"
                 :: "r"(saddr), "l"(gmem_src), "r"(sz));
}
__device__ __forceinline__ void cp_commit() {
    asm volatile("cp.async.commit_group;\n");
}
template <int N>
__device__ __forceinline__ void cp_wait() {
    asm volatile("cp.async.wait_group %0;\n" :: "n"(N));
}

// ---------------- conversion kernels ----------------
__global__ void cvt_f16_vec(const float4* __restrict__ in,
                            __half2* __restrict__ out, int n4) {
    int i = blockIdx.x * blockDim.x + threadIdx.x;
    if (i < n4) {
        float4 v = in[i];
        out[2 * i] = __floats2half2_rn(v.x, v.y);
        out[2 * i + 1] = __floats2half2_rn(v.z, v.w);
    }
}

// batched transpose W[K,N] -> Wt[N,K] f16; grid (16,16,22), block (32,8)
struct TP22 {
    const float* in[22];
    __half* out[22];
};
__global__ void transpose_cvt16_all(TP22 tp) {
    __shared__ float tile[32][33];
    const float* A = tp.in[blockIdx.z];
    __half* O = tp.out[blockIdx.z];
    int x = blockIdx.x * 32 + threadIdx.x;
    int y0 = blockIdx.y * 32 + threadIdx.y;
#pragma unroll
    for (int i = 0; i < 32; i += 8)
        tile[threadIdx.y + i][threadIdx.x] = A[(size_t)(y0 + i) * HH + x];
    __syncthreads();
    int ox = blockIdx.y * 32 + threadIdx.x;
    int oy0 = blockIdx.x * 32 + threadIdx.y;
#pragma unroll
    for (int i = 0; i < 32; i += 8)
        O[(size_t)(oy0 + i) * HH + ox] =
            __float2half_rn(tile[threadIdx.x][threadIdx.y + i]);
}

// ---------------- degree + CSR build ----------------
__global__ void degree_count(const int* __restrict__ src, const int* __restrict__ dst,
                             float* __restrict__ rdo, float* __restrict__ rdi,
                             int* __restrict__ cnt) {
    int idx = blockIdx.x * blockDim.x + threadIdx.x;
    if (idx >= RR * EE) return;
    int r = idx / EE;
    int d = dst[idx];
    atomicAdd(&rdo[(size_t)r * NN + src[idx]], 1.0f);
    atomicAdd(&rdi[(size_t)r * NN + d], 1.0f);
    atomicAdd(&cnt[(size_t)r * NN + d], 1);
}

__global__ void degree_finalize2(float* __restrict__ a, float* __restrict__ b,
                                 int n) {
    int idx = blockIdx.x * blockDim.x + threadIdx.x;
    if (idx < n) {
        a[idx] = rsqrtf(fmaxf(a[idx], 1.0f));
        b[idx] = rsqrtf(fmaxf(b[idx], 1.0f));
    }
}

// 3-phase scan: chunk partials -> serial mid -> apply
__global__ __launch_bounds__(1024) void scan_partial(const int* __restrict__ cnt,
                                                     int* __restrict__ off,
                                                     int* __restrict__ psum) {
    int r = blockIdx.x / NCH;
    int ch = blockIdx.x % NCH;
    int idx = ch * 1024 + threadIdx.x;
    int val = (idx < NN) ? cnt[(size_t)r * NN + idx] : 0;
    __shared__ int warp_sums[32];
    int lane = threadIdx.x & 31;
    int w = threadIdx.x >> 5;
    int x = val;
#pragma unroll
    for (int s = 1; s < 32; s <<= 1) {
        int y = __shfl_up_sync(0xffffffffu, x, s);
        if (lane >= s) x += y;
    }
    if (lane == 31) warp_sums[w] = x;
    __syncthreads();
    if (w == 0) {
        int y = warp_sums[lane];
#pragma unroll
        for (int s = 1; s < 32; s <<= 1) {
            int z = __shfl_up_sync(0xffffffffu, y, s);
            if (lane >= s) y += z;
        }
        warp_sums[lane] = y;
    }
    __syncthreads();
    int excl = x - val + ((w > 0) ? warp_sums[w - 1] : 0);
    if (idx < NN) off[(size_t)r * (NN + 1) + idx] = excl;
    if (threadIdx.x == 0) psum[r * 64 + ch] = 0;  // ensure defined
    __syncthreads();
    if (threadIdx.x == 1023) psum[r * 64 + ch] = warp_sums[31];
}

__global__ void scan_mid(int* __restrict__ psum, int* __restrict__ off) {
    int r = blockIdx.x;  // one thread per relation
    if (threadIdx.x != 0) return;
    int run = 0;
    for (int i = 0; i < NCH; i++) {
        int v = psum[r * 64 + i];
        psum[r * 64 + i] = run;
        run += v;
    }
    off[(size_t)r * (NN + 1) + NN] = run;
}

__global__ __launch_bounds__(1024) void scan_apply(int* __restrict__ off,
                                                   const int* __restrict__ psum) {
    int r = blockIdx.x / NCH;
    int ch = blockIdx.x % NCH;
    int idx = ch * 1024 + threadIdx.x;
    if (idx < NN) off[(size_t)r * (NN + 1) + idx] += psum[r * 64 + ch];
}

__global__ void build_adj(const int* __restrict__ dst, const int* __restrict__ off,
                          int* __restrict__ cur, int* __restrict__ eid) {
    int idx = blockIdx.x * blockDim.x + threadIdx.x;
    if (idx >= RR * EE) return;
    int r = idx / EE;
    int e = idx - r * EE;
    int d = dst[idx];
    int pos = atomicAdd(&cur[(size_t)r * NN + d], 1);
    eid[(size_t)r * EE + off[(size_t)r * (NN + 1) + d] + pos] = e;
}

// ---------------- batched FP16 tensor-core GEMM (up to 9 weights, shared A) ---
#define AW 36
#define AS_WORDS (128 * AW)
#define BS_WORDS (128 * AW)
#define GEMM_SMEM ((2 * AS_WORDS + 2 * BS_WORDS) * 4)

struct G9 {
    const __half* W[9];
    __half* C[9];
    const float* rs[9];
    const float* b[9];
};

__global__ __launch_bounds__(256) void f16gemm9(
    const __half* __restrict__ A, G9 args, int M) {
    extern __shared__ unsigned sm[];
    unsigned* As = sm;
    unsigned* Bs = sm + 2 * AS_WORDS;

    const int z = blockIdx.z;
    const __half* Wt = args.W[z];
    const int bm = blockIdx.y * 128;
    const int bn = blockIdx.x * 128;
    const int tid = threadIdx.x;
    const int warp = tid >> 5;
    const int lane = tid & 31;
    const int g = lane >> 2;
    const int t = lane & 3;
    const int wm = (warp >> 1) * 32;
    const int wn = (warp & 1) * 64;

    float acc[2][8][4];
#pragma unroll
    for (int i = 0; i < 2; i++)
#pragma unroll
        for (int j = 0; j < 8; j++)
#pragma unroll
            for (int q = 0; q < 4; q++) acc[i][j][q] = 0.0f;

    int l_row[4], l_c[4];
#pragma unroll
    for (int i = 0; i < 4; i++) {
        int slot = tid + i * 256;
        l_row[i] = slot >> 3;
        l_c[i] = slot & 7;
    }

    const unsigned as_base = (unsigned)__cvta_generic_to_shared(As);
    const unsigned bs_base = (unsigned)__cvta_generic_to_shared(Bs);
    const unsigned a_lane_off =
        ((wm + (lane & 7) + ((lane >> 3) & 1) * 8) * AW + ((lane >> 4) & 1) * 4) * 4;
    const unsigned b_lane_off =
        ((wn + (lane & 7) + ((lane >> 4) & 1) * 8) * AW + ((lane >> 3) & 1) * 4) * 4;

#define LOAD_TILE(k0, st)                                                          \
    do {                                                                           \
        unsigned* as = As + (st)*AS_WORDS;                                         \
        unsigned* bs = Bs + (st)*BS_WORDS;                                         \
        _Pragma("unroll") for (int i = 0; i < 4; i++) {                            \
            int row = l_row[i], c = l_c[i];                                        \
            int gr = bm + row;                                                     \
            cp16(as + row * AW + c * 4,                                            \
                 A + (size_t)gr * 512 + (k0) + c * 8, gr < M);                     \
            cp16(bs + row * AW + c * 4,                                            \
                 Wt + (size_t)(bn + row) * 512 + (k0) + c * 8, true);              \
        }                                                                          \
    } while (0)

    LOAD_TILE(0, 0);
    cp_commit();
    int stage = 0;
#pragma unroll 1
    for (int it = 0; it < 8; it++) {
        if (it + 1 < 8) {
            LOAD_TILE((it + 1) * 64, stage ^ 1);
            cp_commit();
            cp_wait<1>();
        } else {
            cp_wait<0>();
        }
        __syncthreads();
        const unsigned a_st = as_base + a_lane_off + stage * (AS_WORDS * 4);
        const unsigned b_st = bs_base + b_lane_off + stage * (BS_WORDS * 4);
#pragma unroll
        for (int ks = 0; ks < 4; ks++) {
            const unsigned kb = ks * 32;
            unsigned afr[2][4];
#pragma unroll
            for (int mt = 0; mt < 2; mt++)
                ldsm_x4(a_st + mt * (16 * AW * 4) + kb,
                        afr[mt][0], afr[mt][1], afr[mt][2], afr[mt][3]);
            unsigned bfr[8][2];
#pragma unroll
            for (int ntp = 0; ntp < 4; ntp++)
                ldsm_x4(b_st + ntp * (16 * AW * 4) + kb,
                        bfr[2 * ntp][0], bfr[2 * ntp][1],
                        bfr[2 * ntp + 1][0], bfr[2 * ntp + 1][1]);
#pragma unroll
            for (int mt = 0; mt < 2; mt++)
#pragma unroll
                for (int nt = 0; nt < 8; nt++)
                    mma_f16(acc[mt][nt], afr[mt], bfr[nt]);
        }
        __syncthreads();
        stage ^= 1;
    }

    __half* C = args.C[z];
    const float* rowscale = args.rs[z];
    const float* bias = args.b[z];
#pragma unroll
    for (int mt = 0; mt < 2; mt++) {
        int r0 = bm + wm + mt * 16 + g;
        int r1 = r0 + 8;
        float s0 = 1.0f, s1 = 1.0f;
        if (rowscale) {
            if (r0 < M) s0 = rowscale[r0];
            if (r1 < M) s1 = rowscale[r1];
        }
#pragma unroll
        for (int nt = 0; nt < 8; nt++) {
            int c = bn + wn + nt * 8 + t * 2;
            float b0 = 0.0f, b1 = 0.0f;
            if (bias) { b0 = bias[c]; b1 = bias[c + 1]; }
            if (r0 < M)
                *(__half2*)(C + (size_t)r0 * 512 + c) =
                    __floats2half2_rn(acc[mt][nt][0] * s0 + b0,
                                      acc[mt][nt][1] * s0 + b1);
            if (r1 < M)
                *(__half2*)(C + (size_t)r1 * 512 + c) =
                    __floats2half2_rn(acc[mt][nt][2] * s1 + b0,
                                      acc[mt][nt][3] * s1 + b1);
        }
    }
}

// ---------------- LN core ----------------
__device__ __forceinline__ float4 ln_elu_core4(
    float4 v, const float* __restrict__ gamma, const float* __restrict__ beta) {
    int t = threadIdx.x;
    float sum = v.x + v.y + v.z + v.w;
    sum = block_reduce_sum_128(sum);
    float u = sum * (1.0f / HH);
    float dx = v.x - u, dy = v.y - u, dz = v.z - u, dw = v.w - u;
    float var = dx * dx + dy * dy + dz * dz + dw * dw;
    var = block_reduce_sum_128(var) * (1.0f / HH);
    float inv = rsqrtf(var + 1e-12f);
    float4 ga = ((const float4*)gamma)[t];
    float4 be = ((const float4*)beta)[t];
    float y0 = ga.x * dx * inv + be.x;
    float y1 = ga.y * dy * inv + be.y;
    float y2 = ga.z * dz * inv + be.z;
    float y3 = ga.w * dw * inv + be.w;
    y0 = (y0 > 0.0f) ? y0 : (expf(y0) - 1.0f);
    y1 = (y1 > 0.0f) ? y1 : (expf(y1) - 1.0f);
    y2 = (y2 > 0.0f) ? y2 : (expf(y2) - 1.0f);
    y3 = (y3 > 0.0f) ? y3 : (expf(y3) - 1.0f);
    return make_float4(y0, y1, y2, y3);
}

__device__ __forceinline__ float4 load4h(const __half* p, int t) {
    uint2 raw = ((const uint2*)p)[t];
    float2 lo = __half22float2(*(__half2*)&raw.x);
    float2 hi = __half22float2(*(__half2*)&raw.y);
    return make_float4(lo.x, lo.y, hi.x, hi.y);
}

// ---------------- mega-fused per-node branch kernel (batched over r) ----------
__global__ __launch_bounds__(128) void fused_branches(
    const int* __restrict__ eid_all, const int* __restrict__ off_all,
    const int* __restrict__ src_all, const __half* __restrict__ go,
    const float* __restrict__ el_all, const float* __restrict__ er_all,
    const float* __restrict__ rdi_all,
    const float* __restrict__ bc_l, const float* __restrict__ gc_l,
    const float* __restrict__ bec_l,
    const float* __restrict__ bg_l, const float* __restrict__ gg_l,
    const float* __restrict__ beg_l,
    const float* __restrict__ bs_l, const float* __restrict__ gs_l,
    const float* __restrict__ bes_l,
    __half* __restrict__ out16) {
    const int n = blockIdx.x;
    const int r = blockIdx.y;
    const int* eid = eid_all + (size_t)r * EE;
    const int* off = off_all + (size_t)r * (NN + 1);
    const int* src = src_all + (size_t)r * EE;
    const __half* Xc = go + (size_t)(r * 3 + 0) * NNHH;
    const __half* f = go + (size_t)(r * 3 + 1) * NNHH;
    const __half* Xs = go + (size_t)(r * 3 + 2) * NNHH;
    const float* el = el_all + (size_t)r * NN * NHEADS;
    const float* er = er_all + (size_t)r * NN * NHEADS;
    const float* rdi = rdi_all + (size_t)r * NN;
    const float* bc = bc_l + r * HH;
    const float* gc = gc_l + r * HH;
    const float* bec = bec_l + r * HH;
    const float* bg = bg_l + r * HH;
    const float* gg = gg_l + r * HH;
    const float* beg = beg_l + r * HH;
    const float* bs_ = bs_l + r * HH;
    const float* gs = gs_l + r * HH;
    const float* bes = bes_l + r * HH;

    int p0 = off[n], p1 = off[n + 1];
    int t = threadIdx.x;
    int h = t >> 4;

    __shared__ float sh_m[NHEADS], sh_invs[NHEADS];
    if (t < NHEADS) {
        float ern = er[n * NHEADS + t];
        float mx = -INFINITY;
        for (int p = p0; p < p1; p++) {
            float x = el[src[eid[p]] * NHEADS + t] + ern;
            x = (x > 0.0f) ? x : 0.2f * x;
            mx = fmaxf(mx, x);
        }
        float s = 0.0f;
        for (int p = p0; p < p1; p++) {
            float x = el[src[eid[p]] * NHEADS + t] + ern;
            x = (x > 0.0f) ? x : 0.2f * x;
            s += expf(x - mx);
        }
        sh_m[t] = mx;
        sh_invs[t] = (s > 0.0f) ? (1.0f / s) : 1.0f;
    }
    __syncthreads();

    float mh = sh_m[h];
    float invs = sh_invs[h];
    float ern = er[n * NHEADS + h];

    float4 ac = make_float4(0.f, 0.f, 0.f, 0.f);
    float4 ag = make_float4(0.f, 0.f, 0.f, 0.f);
    for (int p = p0; p < p1; p++) {
        int e = eid[p];
        int sn = src[e];
        float4 rc = load4h(Xc + (size_t)sn * HH, t);
        float4 rg = load4h(f + (size_t)sn * HH, t);
        float x = el[sn * NHEADS + h] + ern;
        x = (x > 0.0f) ? x : 0.2f * x;
        float a = expf(x - mh) * invs;
        ac.x += rc.x; ac.y += rc.y; ac.z += rc.z; ac.w += rc.w;
        ag.x += a * rg.x; ag.y += a * rg.y; ag.z += a * rg.z; ag.w += a * rg.w;
    }

    float sc = rdi[n];
    float4 bb = ((const float4*)bc)[t];
    float4 v = make_float4(ac.x * sc + bb.x, ac.y * sc + bb.y,
                           ac.z * sc + bb.z, ac.w * sc + bb.w);
    float4 y = ln_elu_core4(v, gc, bec);
    float rx = y.x, ry = y.y, rz = y.z, rw = y.w;

    bb = ((const float4*)bg)[t];
    v = make_float4(ag.x + bb.x, ag.y + bb.y, ag.z + bb.z, ag.w + bb.w);
    y = ln_elu_core4(v, gg, beg);
    rx += y.x; ry += y.y; rz += y.z; rw += y.w;

    float4 xs = load4h(Xs + (size_t)n * HH, t);
    bb = ((const float4*)bs_)[t];
    v = make_float4(xs.x + bb.x, xs.y + bb.y, xs.z + bb.z, xs.w + bb.w);
    y = ln_elu_core4(v, gs, bes);
    rx += y.x; ry += y.y; rz += y.z; rw += y.w;

    __half2* op = (__half2*)(out16 + (size_t)n * (RR * HH) + (size_t)r * HH + 4 * t);
    op[0] = __floats2half2_rn(rx, ry);
    op[1] = __floats2half2_rn(rz, rw);
}

// ---------------- GAT attn-score precompute (batched over r) ----------------
__global__ void gat_el_er(const __half* __restrict__ go,
                          const float* __restrict__ al_l,
                          const float* __restrict__ ar_l,
                          float* __restrict__ el_all, float* __restrict__ er_all) {
    int idx = blockIdx.x * blockDim.x + threadIdx.x;
    if (idx >= NN * NHEADS) return;
    int r = blockIdx.y;
    int n = idx >> 3;
    int hh = idx & 7;
    const __half* f = go + (size_t)(r * 3 + 1) * NNHH;
    const __half* fr = f + (size_t)n * HH + hh * DHH;
    const float* a1 = al_l + r * NHEADS * DHH + hh * DHH;
    const float* a2 = ar_l + r * NHEADS * DHH + hh * DHH;
    float s1 = 0.0f, s2 = 0.0f;
#pragma unroll 8
    for (int d = 0; d < DHH; d++) {
        float fv = __half2float(fr[d]);
        s1 += fv * a1[d];
        s2 += fv * a2[d];
    }
    el_all[(size_t)r * NN * NHEADS + idx] = s1;
    er_all[(size_t)r * NN * NHEADS + idx] = s2;
}

// ---------------- relation MHA (3 tokens) + mean (+ optional fused classify) --
__global__ __launch_bounds__(256) void mha_mean(
    const __half* __restrict__ q, const __half* __restrict__ k,
    const __half* __restrict__ v, __half* __restrict__ out16,
    const float* __restrict__ Wout, const float* __restrict__ bout,
    float* __restrict__ logits) {
    int n = blockIdx.x;
    int hd = threadIdx.x >> 5;
    int lane = threadIdx.x & 31;
    size_t base = (size_t)n * RR * HH + hd * DHH;
    float qa[RR], qb[RR], ka[RR], kb[RR], va[RR], vb[RR];
#pragma unroll
    for (int r = 0; r < RR; r++) {
        size_t off = base + (size_t)r * HH;
        qa[r] = __half2float(q[off + lane]);
        qb[r] = __half2float(q[off + lane + 32]);
        ka[r] = __half2float(k[off + lane]);
        kb[r] = __half2float(k[off + lane + 32]);
        va[r] = __half2float(v[off + lane]);
        vb[r] = __half2float(v[off + lane + 32]);
    }
    float sc[RR][RR];
#pragma unroll
    for (int r = 0; r < RR; r++)
#pragma unroll
        for (int t = 0; t < RR; t++) {
            float p = qa[r] * ka[t] + qb[r] * kb[t];
#pragma unroll
            for (int o = 16; o > 0; o >>= 1) p += __shfl_xor_sync(0xffffffffu, p, o);
            sc[r][t] = p * 0.125f;
        }
    float w0 = 0.0f, w1 = 0.0f, w2 = 0.0f;
#pragma unroll
    for (int r = 0; r < RR; r++) {
        float mx = fmaxf(sc[r][0], fmaxf(sc[r][1], sc[r][2]));
        float e0 = expf(sc[r][0] - mx);
        float e1 = expf(sc[r][1] - mx);
        float e2 = expf(sc[r][2] - mx);
        float inv = 1.0f / (e0 + e1 + e2);
        w0 += e0 * inv;
        w1 += e1 * inv;
        w2 += e2 * inv;
    }
    const float third = 1.0f / 3.0f;
    float oa = (w0 * va[0] + w1 * va[1] + w2 * va[2]) * third;
    float ob = (w0 * vb[0] + w1 * vb[1] + w2 * vb[2]) * third;
    size_t o0 = (size_t)n * HH + hd * DHH + lane;
    out16[o0] = __float2half_rn(oa);
    out16[o0 + 32] = __float2half_rn(ob);

    if (Wout) {
        __shared__ float shh[HH];
        shh[hd * DHH + lane] = oa;
        shh[hd * DHH + lane + 32] = ob;
        __syncthreads();
        int c = threadIdx.x >> 3;   // 0..31
        int seg = threadIdx.x & 7;  // 0..7
        float s = 0.0f;
        if (c < NCLSS) {
            int j0 = seg * 64;
#pragma unroll 16
            for (int j = j0; j < j0 + 64; j++) s += shh[j] * Wout[j * NCLSS + c];
        }
#pragma unroll
        for (int o = 4; o > 0; o >>= 1) s += __shfl_down_sync(0xffffffffu, s, o);
        if (seg == 0 && c < NCLSS) logits[(size_t)n * NCLSS + c] = s + bout[c];
    }
}

// ---------------- launch ----------------
extern "C" void kernel_launch(void* const* d_in, const int* in_sizes, int n_in,
                              void* d_out, int out_size) {
    const float* feature = (const float*)d_in[0];
    const int* src = (const int*)d_in[1];
    const int* dst = (const int*)d_in[2];
    const float* Wc = (const float*)d_in[3];
    const float* bc = (const float*)d_in[4];
    const float* gc = (const float*)d_in[5];
    const float* betac = (const float*)d_in[6];
    const float* Wg = (const float*)d_in[7];
    const float* bg = (const float*)d_in[8];
    const float* al = (const float*)d_in[9];
    const float* ar = (const float*)d_in[10];
    const float* gg = (const float*)d_in[11];
    const float* betag = (const float*)d_in[12];
    const float* Ws = (const float*)d_in[13];
    const float* bs = (const float*)d_in[14];
    const float* gs = (const float*)d_in[15];
    const float* betas = (const float*)d_in[16];
    const float* Wq = (const float*)d_in[17];
    const float* bq = (const float*)d_in[18];
    const float* Wk = (const float*)d_in[19];
    const float* bk = (const float*)d_in[20];
    const float* Wv = (const float*)d_in[21];
    const float* bv = (const float*)d_in[22];
    const float* Wout = (const float*)d_in[23];
    const float* bout = (const float*)d_in[24];
    float* out = (float*)d_out;

    float *p_rdo, *p_rdi, *p_el, *p_er;
    __half *p_h16, *p_go16, *p_stk16, *p_w16, *p_q, *p_k, *p_v;
    int *p_cnt, *p_cur, *p_off, *p_eid, *p_psum;
    cudaGetSymbolAddress((void**)&p_h16, g_h16);
    cudaGetSymbolAddress((void**)&p_go16, g_go16);
    cudaGetSymbolAddress((void**)&p_stk16, g_stk16);
    cudaGetSymbolAddress((void**)&p_q, g_q);
    cudaGetSymbolAddress((void**)&p_k, g_k);
    cudaGetSymbolAddress((void**)&p_v, g_v);
    cudaGetSymbolAddress((void**)&p_w16, g_w16);
    cudaGetSymbolAddress((void**)&p_rdo, g_rdo);
    cudaGetSymbolAddress((void**)&p_rdi, g_rdi);
    cudaGetSymbolAddress((void**)&p_el, g_el);
    cudaGetSymbolAddress((void**)&p_er, g_er);
    cudaGetSymbolAddress((void**)&p_cnt, g_cnt);
    cudaGetSymbolAddress((void**)&p_cur, g_cur);
    cudaGetSymbolAddress((void**)&p_off, g_off);
    cudaGetSymbolAddress((void**)&p_eid, g_eid);
    cudaGetSymbolAddress((void**)&p_psum, g_psum);

    cudaFuncSetAttribute(f16gemm9, cudaFuncAttributeMaxDynamicSharedMemorySize,
                         GEMM_SMEM);

    const size_t WHH = (size_t)HH * HH;
    __half* w16_Wc = p_w16;
    __half* w16_Wg = p_w16 + 6 * WHH;
    __half* w16_Ws = p_w16 + 12 * WHH;
    __half* w16_Wq = p_w16 + 18 * WHH;
    __half* w16_Wk = p_w16 + 20 * WHH;
    __half* w16_Wv = p_w16 + 22 * WHH;

    // batched transpose+convert (22 matrices) + feature cvt
    {
        TP22 tp;
        for (int i = 0; i < 6; i++) {
            tp.in[i] = Wc + (size_t)i * WHH;
            tp.out[i] = w16_Wc + (size_t)i * WHH;
            tp.in[6 + i] = Wg + (size_t)i * WHH;
            tp.out[6 + i] = w16_Wg + (size_t)i * WHH;
            tp.in[12 + i] = Ws + (size_t)i * WHH;
            tp.out[12 + i] = w16_Ws + (size_t)i * WHH;
        }
        for (int i = 0; i < 2; i++) {
            tp.in[18 + i] = Wq + (size_t)i * WHH;
            tp.out[18 + i] = w16_Wq + (size_t)i * WHH;
            tp.in[20 + i] = Wk + (size_t)i * WHH;
            tp.out[20 + i] = w16_Wk + (size_t)i * WHH;
        }
        // Wv goes in remaining z? pack: use second kernel for Wv (2 matrices)
        transpose_cvt16_all<<<dim3(16, 16, 22), dim3(32, 8)>>>(tp);
        TP22 tpv;
        for (int i = 0; i < 2; i++) {
            tpv.in[i] = Wv + (size_t)i * WHH;
            tpv.out[i] = w16_Wv + (size_t)i * WHH;
        }
        transpose_cvt16_all<<<dim3(16, 16, 2), dim3(32, 8)>>>(tpv);
        int n4f = (int)(NNHH / 4);
        cvt_f16_vec<<<(n4f + 255) / 256, 256>>>((const float4*)feature,
                                                (__half2*)p_h16, n4f);
    }

    cudaMemsetAsync(p_rdo, 0, (size_t)RR * NN * sizeof(float), 0);
    cudaMemsetAsync(p_rdi, 0, (size_t)RR * NN * sizeof(float), 0);
    cudaMemsetAsync(p_cnt, 0, (size_t)RR * NN * sizeof(int), 0);
    cudaMemsetAsync(p_cur, 0, (size_t)RR * NN * sizeof(int), 0);
    degree_count<<<(RR * EE + 255) / 256, 256>>>(src, dst, p_rdo, p_rdi, p_cnt);
    degree_finalize2<<<(RR * NN + 255) / 256, 256>>>(p_rdo, p_rdi, RR * NN);
    scan_partial<<<RR * NCH, 1024>>>(p_cnt, p_off, p_psum);
    scan_mid<<<RR, 32>>>(p_psum, p_off);
    scan_apply<<<RR * NCH, 1024>>>(p_off, p_psum);
    build_adj<<<(RR * EE + 255) / 256, 256>>>(dst, p_off, p_cur, p_eid);

    const dim3 gemm_grid_n(4, (NN + 127) / 128, 9);
    const dim3 gemm_grid_nr(4, (NN * RR + 127) / 128, 3);
    const dim3 elgrid((NN * NHEADS + 255) / 256, 3);
    const dim3 fgrid(NN, 3);

    for (int l = 0; l < LL; l++) {
        const size_t lbase = (size_t)l * RR;

        G9 a9;
        for (int r = 0; r < RR; r++) {
            const size_t lr = lbase + r;
            a9.W[r * 3 + 0] = w16_Wc + lr * WHH;
            a9.W[r * 3 + 1] = w16_Wg + lr * WHH;
            a9.W[r * 3 + 2] = w16_Ws + lr * WHH;
            for (int bI = 0; bI < 3; bI++) {
                a9.C[r * 3 + bI] = p_go16 + (size_t)(r * 3 + bI) * NNHH;
                a9.b[r * 3 + bI] = nullptr;
            }
            a9.rs[r * 3 + 0] = p_rdo + (size_t)r * NN;
            a9.rs[r * 3 + 1] = nullptr;
            a9.rs[r * 3 + 2] = nullptr;
        }
        f16gemm9<<<gemm_grid_n, 256, GEMM_SMEM>>>(p_h16, a9, NN);

        gat_el_er<<<elgrid, 256>>>(p_go16, al + lbase * NHEADS * DHH,
                                   ar + lbase * NHEADS * DHH, p_el, p_er);
        fused_branches<<<fgrid, 128>>>(
            p_eid, p_off, src, p_go16, p_el, p_er, p_rdi,
            bc + lbase * HH, gc + lbase * HH, betac + lbase * HH,
            bg + lbase * HH, gg + lbase * HH, betag + lbase * HH,
            bs + lbase * HH, gs + lbase * HH, betas + lbase * HH,
            p_stk16);

        G9 aq;
        aq.W[0] = w16_Wq + (size_t)l * WHH;
        aq.W[1] = w16_Wk + (size_t)l * WHH;
        aq.W[2] = w16_Wv + (size_t)l * WHH;
        aq.C[0] = p_q;
        aq.C[1] = p_k;
        aq.C[2] = p_v;
        aq.rs[0] = nullptr; aq.rs[1] = nullptr; aq.rs[2] = nullptr;
        aq.b[0] = bq + (size_t)l * HH;
        aq.b[1] = bk + (size_t)l * HH;
        aq.b[2] = bv + (size_t)l * HH;
        for (int zz = 3; zz < 9; zz++) {
            aq.W[zz] = nullptr; aq.C[zz] = nullptr;
            aq.rs[zz] = nullptr; aq.b[zz] = nullptr;
        }
        f16gemm9<<<gemm_grid_nr, 256, GEMM_SMEM>>>(p_stk16, aq, NN * RR);

        if (l == LL - 1) {
            mha_mean<<<NN, 256>>>(p_q, p_k, p_v, p_h16, Wout, bout, out);
        } else {
            mha_mean<<<NN, 256>>>(p_q, p_k, p_v, p_h16, nullptr, nullptr,
                                  nullptr);
        }
    }
}

// round 17
// speedup vs baseline: 1.1359x; 1.1359x over previous
#include <cuda_runtime.h>
#include <cuda_fp16.h>
#include <math.h>
#include <stdint.h>

#define NN 50000
#define EE 150000
#define RR 3
#define LL 2
#define HH 512
#define NHEADS 8
#define DHH 64
#define NCLSS 23
#define NNHH ((size_t)NN * HH)
#define NCH 49  // ceil(NN/1024)

// ---------------- scratch (device globals; no allocs allowed) ----------------
__device__ float g_h[NNHH];
__device__ __half g_h16[NNHH];
__device__ __half g_go16[(size_t)9 * NNHH];
__device__ __half g_stk16[(size_t)NN * RR * HH];
__device__ __half g_q[(size_t)NN * RR * HH];
__device__ __half g_k[(size_t)NN * RR * HH];
__device__ __half g_v[(size_t)NN * RR * HH];
__device__ __half g_w16[(size_t)24 * HH * HH];  // TRANSPOSED [N][K] f16 weights
__device__ float g_rdo[(size_t)RR * NN];
__device__ float g_rdi[(size_t)RR * NN];
__device__ float g_el[(size_t)RR * NN * NHEADS];
__device__ float g_er[(size_t)RR * NN * NHEADS];
// CSR (dst-indexed) per relation
__device__ int g_cnt[(size_t)RR * NN];
__device__ int g_cur[(size_t)RR * NN];
__device__ int g_off[(size_t)RR * (NN + 1)];
__device__ int g_eid[(size_t)RR * EE];
__device__ int g_psum[RR * 64];

// ---------------- helpers ----------------
__device__ __forceinline__ float block_reduce_sum_128(float val) {
    __shared__ float sh[32];
    __syncthreads();
    int lane = threadIdx.x & 31;
    int wid = threadIdx.x >> 5;
#pragma unroll
    for (int o = 16; o > 0; o >>= 1) val += __shfl_xor_sync(0xffffffffu, val, o);
    if (lane == 0) sh[wid] = val;
    __syncthreads();
    if (wid == 0) {
        float v = (lane < (blockDim.x >> 5)) ? sh[lane] : 0.0f;
#pragma unroll
        for (int o = 16; o > 0; o >>= 1) v += __shfl_xor_sync(0xffffffffu, v, o);
        if (lane == 0) sh[0] = v;
    }
    __syncthreads();
    return sh[0];
}

__device__ __forceinline__ void mma_f16(float* d, const unsigned* a, const unsigned* b) {
    asm volatile(
        "mma.sync.aligned.m16n8k16.row.col.f32.f16.f16.f32 "
        "{%0,%1,%2,%3}, {%4,%5,%6,%7}, {%8,%9}, {%0,%1,%2,%3};"
        : "+f"(d[0]), "+f"(d[1]), "+f"(d[2]), "+f"(d[3])
        : "r"(a[0]), "r"(a[1]), "r"(a[2]), "r"(a[3]), "r"(b[0]), "r"(b[1]));
}

__device__ __forceinline__ void ldsm_x4(unsigned addr, unsigned& r0, unsigned& r1,
                                        unsigned& r2, unsigned& r3) {
    asm volatile(
        "ldmatrix.sync.aligned.m8n8.x4.shared.b16 {%0,%1,%2,%3}, [%4];"
        : "=r"(r0), "=r"(r1), "=r"(r2), "=r"(r3)
        : "r"(addr));
}

__device__ __forceinline__ void cp16(void* smem_dst, const void* gmem_src, bool pred) {
    unsigned saddr = (unsigned)__cvta_generic_to_shared(smem_dst);
    int sz = pred ? 16 : 0;
    asm volatile("cp.async.cg.shared.global [%0], [%1], 16, %2;\n"
                 :: "r"(saddr), "l"(gmem_src), "r"(sz));
}
__device__ __forceinline__ void cp_commit() {
    asm volatile("cp.async.commit_group;\n");
}
template <int N>
__device__ __forceinline__ void cp_wait() {
    asm volatile("cp.async.wait_group %0;\n" :: "n"(N));
}

// ---------------- conversion kernels ----------------
__global__ void cvt_f16_vec(const float4* __restrict__ in,
                            __half2* __restrict__ out, int n4) {
    int i = blockIdx.x * blockDim.x + threadIdx.x;
    if (i < n4) {
        float4 v = in[i];
        out[2 * i] = __floats2half2_rn(v.x, v.y);
        out[2 * i + 1] = __floats2half2_rn(v.z, v.w);
    }
}

// batched transpose W[K,N] -> Wt[N,K] f16; grid (16,16,nz), block (32,8)
struct TP22 {
    const float* in[22];
    __half* out[22];
};
__global__ void transpose_cvt16_all(TP22 tp) {
    __shared__ float tile[32][33];
    const float* A = tp.in[blockIdx.z];
    __half* O = tp.out[blockIdx.z];
    int x = blockIdx.x * 32 + threadIdx.x;
    int y0 = blockIdx.y * 32 + threadIdx.y;
#pragma unroll
    for (int i = 0; i < 32; i += 8)
        tile[threadIdx.y + i][threadIdx.x] = A[(size_t)(y0 + i) * HH + x];
    __syncthreads();
    int ox = blockIdx.y * 32 + threadIdx.x;
    int oy0 = blockIdx.x * 32 + threadIdx.y;
#pragma unroll
    for (int i = 0; i < 32; i += 8)
        O[(size_t)(oy0 + i) * HH + ox] =
            __float2half_rn(tile[threadIdx.x][threadIdx.y + i]);
}

// ---------------- degree + CSR build ----------------
__global__ void degree_count(const int* __restrict__ src, const int* __restrict__ dst,
                             float* __restrict__ rdo, float* __restrict__ rdi,
                             int* __restrict__ cnt) {
    int idx = blockIdx.x * blockDim.x + threadIdx.x;
    if (idx >= RR * EE) return;
    int r = idx / EE;
    int d = dst[idx];
    atomicAdd(&rdo[(size_t)r * NN + src[idx]], 1.0f);
    atomicAdd(&rdi[(size_t)r * NN + d], 1.0f);
    atomicAdd(&cnt[(size_t)r * NN + d], 1);
}

__global__ void degree_finalize2(float* __restrict__ a, float* __restrict__ b,
                                 int n) {
    int idx = blockIdx.x * blockDim.x + threadIdx.x;
    if (idx < n) {
        a[idx] = rsqrtf(fmaxf(a[idx], 1.0f));
        b[idx] = rsqrtf(fmaxf(b[idx], 1.0f));
    }
}

// 3-phase scan: chunk partials -> serial mid -> apply
__global__ __launch_bounds__(1024) void scan_partial(const int* __restrict__ cnt,
                                                     int* __restrict__ off,
                                                     int* __restrict__ psum) {
    int r = blockIdx.x / NCH;
    int ch = blockIdx.x % NCH;
    int idx = ch * 1024 + threadIdx.x;
    int val = (idx < NN) ? cnt[(size_t)r * NN + idx] : 0;
    __shared__ int warp_sums[32];
    int lane = threadIdx.x & 31;
    int w = threadIdx.x >> 5;
    int x = val;
#pragma unroll
    for (int s = 1; s < 32; s <<= 1) {
        int y = __shfl_up_sync(0xffffffffu, x, s);
        if (lane >= s) x += y;
    }
    if (lane == 31) warp_sums[w] = x;
    __syncthreads();
    if (w == 0) {
        int y = warp_sums[lane];
#pragma unroll
        for (int s = 1; s < 32; s <<= 1) {
            int z = __shfl_up_sync(0xffffffffu, y, s);
            if (lane >= s) y += z;
        }
        warp_sums[lane] = y;
    }
    __syncthreads();
    int excl = x - val + ((w > 0) ? warp_sums[w - 1] : 0);
    if (idx < NN) off[(size_t)r * (NN + 1) + idx] = excl;
    if (threadIdx.x == 1023) psum[r * 64 + ch] = warp_sums[31];
}

__global__ void scan_mid(int* __restrict__ psum, int* __restrict__ off) {
    int r = blockIdx.x;
    if (threadIdx.x != 0) return;
    int run = 0;
    for (int i = 0; i < NCH; i++) {
        int v = psum[r * 64 + i];
        psum[r * 64 + i] = run;
        run += v;
    }
    off[(size_t)r * (NN + 1) + NN] = run;
}

__global__ __launch_bounds__(1024) void scan_apply(int* __restrict__ off,
                                                   const int* __restrict__ psum) {
    int r = blockIdx.x / NCH;
    int ch = blockIdx.x % NCH;
    int idx = ch * 1024 + threadIdx.x;
    if (idx < NN) off[(size_t)r * (NN + 1) + idx] += psum[r * 64 + ch];
}

__global__ void build_adj(const int* __restrict__ dst, const int* __restrict__ off,
                          int* __restrict__ cur, int* __restrict__ eid) {
    int idx = blockIdx.x * blockDim.x + threadIdx.x;
    if (idx >= RR * EE) return;
    int r = idx / EE;
    int e = idx - r * EE;
    int d = dst[idx];
    int pos = atomicAdd(&cur[(size_t)r * NN + d], 1);
    eid[(size_t)r * EE + off[(size_t)r * (NN + 1) + d] + pos] = e;
}

// ---------------- batched FP16 tensor-core GEMM (up to 9 weights, shared A) ---
#define AW 36
#define AS_WORDS (128 * AW)
#define BS_WORDS (128 * AW)
#define GEMM_SMEM ((2 * AS_WORDS + 2 * BS_WORDS) * 4)

struct G9 {
    const __half* W[9];
    __half* C[9];
    const float* rs[9];
    const float* b[9];
};

__global__ __launch_bounds__(256) void f16gemm9(
    const __half* __restrict__ A, G9 args, int M) {
    extern __shared__ unsigned sm[];
    unsigned* As = sm;
    unsigned* Bs = sm + 2 * AS_WORDS;

    const int z = blockIdx.z;
    const __half* Wt = args.W[z];
    const int bm = blockIdx.y * 128;
    const int bn = blockIdx.x * 128;
    const int tid = threadIdx.x;
    const int warp = tid >> 5;
    const int lane = tid & 31;
    const int g = lane >> 2;
    const int t = lane & 3;
    const int wm = (warp >> 1) * 32;
    const int wn = (warp & 1) * 64;

    float acc[2][8][4];
#pragma unroll
    for (int i = 0; i < 2; i++)
#pragma unroll
        for (int j = 0; j < 8; j++)
#pragma unroll
            for (int q = 0; q < 4; q++) acc[i][j][q] = 0.0f;

    int l_row[4], l_c[4];
#pragma unroll
    for (int i = 0; i < 4; i++) {
        int slot = tid + i * 256;
        l_row[i] = slot >> 3;
        l_c[i] = slot & 7;
    }

    const unsigned as_base = (unsigned)__cvta_generic_to_shared(As);
    const unsigned bs_base = (unsigned)__cvta_generic_to_shared(Bs);
    const unsigned a_lane_off =
        ((wm + (lane & 7) + ((lane >> 3) & 1) * 8) * AW + ((lane >> 4) & 1) * 4) * 4;
    const unsigned b_lane_off =
        ((wn + (lane & 7) + ((lane >> 4) & 1) * 8) * AW + ((lane >> 3) & 1) * 4) * 4;

#define LOAD_TILE(k0, st)                                                          \
    do {                                                                           \
        unsigned* as = As + (st)*AS_WORDS;                                         \
        unsigned* bs = Bs + (st)*BS_WORDS;                                         \
        _Pragma("unroll") for (int i = 0; i < 4; i++) {                            \
            int row = l_row[i], c = l_c[i];                                        \
            int gr = bm + row;                                                     \
            cp16(as + row * AW + c * 4,                                            \
                 A + (size_t)gr * 512 + (k0) + c * 8, gr < M);                     \
            cp16(bs + row * AW + c * 4,                                            \
                 Wt + (size_t)(bn + row) * 512 + (k0) + c * 8, true);              \
        }                                                                          \
    } while (0)

    LOAD_TILE(0, 0);
    cp_commit();
    int stage = 0;
#pragma unroll 1
    for (int it = 0; it < 8; it++) {
        if (it + 1 < 8) {
            LOAD_TILE((it + 1) * 64, stage ^ 1);
            cp_commit();
            cp_wait<1>();
        } else {
            cp_wait<0>();
        }
        __syncthreads();
        const unsigned a_st = as_base + a_lane_off + stage * (AS_WORDS * 4);
        const unsigned b_st = bs_base + b_lane_off + stage * (BS_WORDS * 4);
#pragma unroll
        for (int ks = 0; ks < 4; ks++) {
            const unsigned kb = ks * 32;
            unsigned afr[2][4];
#pragma unroll
            for (int mt = 0; mt < 2; mt++)
                ldsm_x4(a_st + mt * (16 * AW * 4) + kb,
                        afr[mt][0], afr[mt][1], afr[mt][2], afr[mt][3]);
            unsigned bfr[8][2];
#pragma unroll
            for (int ntp = 0; ntp < 4; ntp++)
                ldsm_x4(b_st + ntp * (16 * AW * 4) + kb,
                        bfr[2 * ntp][0], bfr[2 * ntp][1],
                        bfr[2 * ntp + 1][0], bfr[2 * ntp + 1][1]);
#pragma unroll
            for (int mt = 0; mt < 2; mt++)
#pragma unroll
                for (int nt = 0; nt < 8; nt++)
                    mma_f16(acc[mt][nt], afr[mt], bfr[nt]);
        }
        __syncthreads();
        stage ^= 1;
    }

    __half* C = args.C[z];
    const float* rowscale = args.rs[z];
    const float* bias = args.b[z];
#pragma unroll
    for (int mt = 0; mt < 2; mt++) {
        int r0 = bm + wm + mt * 16 + g;
        int r1 = r0 + 8;
        float s0 = 1.0f, s1 = 1.0f;
        if (rowscale) {
            if (r0 < M) s0 = rowscale[r0];
            if (r1 < M) s1 = rowscale[r1];
        }
#pragma unroll
        for (int nt = 0; nt < 8; nt++) {
            int c = bn + wn + nt * 8 + t * 2;
            float b0 = 0.0f, b1 = 0.0f;
            if (bias) { b0 = bias[c]; b1 = bias[c + 1]; }
            if (r0 < M)
                *(__half2*)(C + (size_t)r0 * 512 + c) =
                    __floats2half2_rn(acc[mt][nt][0] * s0 + b0,
                                      acc[mt][nt][1] * s0 + b1);
            if (r1 < M)
                *(__half2*)(C + (size_t)r1 * 512 + c) =
                    __floats2half2_rn(acc[mt][nt][2] * s1 + b0,
                                      acc[mt][nt][3] * s1 + b1);
        }
    }
}

// ---------------- LN core ----------------
__device__ __forceinline__ float4 ln_elu_core4(
    float4 v, const float* __restrict__ gamma, const float* __restrict__ beta) {
    int t = threadIdx.x;
    float sum = v.x + v.y + v.z + v.w;
    sum = block_reduce_sum_128(sum);
    float u = sum * (1.0f / HH);
    float dx = v.x - u, dy = v.y - u, dz = v.z - u, dw = v.w - u;
    float var = dx * dx + dy * dy + dz * dz + dw * dw;
    var = block_reduce_sum_128(var) * (1.0f / HH);
    float inv = rsqrtf(var + 1e-12f);
    float4 ga = ((const float4*)gamma)[t];
    float4 be = ((const float4*)beta)[t];
    float y0 = ga.x * dx * inv + be.x;
    float y1 = ga.y * dy * inv + be.y;
    float y2 = ga.z * dz * inv + be.z;
    float y3 = ga.w * dw * inv + be.w;
    y0 = (y0 > 0.0f) ? y0 : (expf(y0) - 1.0f);
    y1 = (y1 > 0.0f) ? y1 : (expf(y1) - 1.0f);
    y2 = (y2 > 0.0f) ? y2 : (expf(y2) - 1.0f);
    y3 = (y3 > 0.0f) ? y3 : (expf(y3) - 1.0f);
    return make_float4(y0, y1, y2, y3);
}

__device__ __forceinline__ float4 load4h(const __half* p, int t) {
    uint2 raw = ((const uint2*)p)[t];
    float2 lo = __half22float2(*(__half2*)&raw.x);
    float2 hi = __half22float2(*(__half2*)&raw.y);
    return make_float4(lo.x, lo.y, hi.x, hi.y);
}

// ---------------- mega-fused per-node branch kernel (batched over r) ----------
__global__ __launch_bounds__(128) void fused_branches(
    const int* __restrict__ eid_all, const int* __restrict__ off_all,
    const int* __restrict__ src_all, const __half* __restrict__ go,
    const float* __restrict__ el_all, const float* __restrict__ er_all,
    const float* __restrict__ rdi_all,
    const float* __restrict__ bc_l, const float* __restrict__ gc_l,
    const float* __restrict__ bec_l,
    const float* __restrict__ bg_l, const float* __restrict__ gg_l,
    const float* __restrict__ beg_l,
    const float* __restrict__ bs_l, const float* __restrict__ gs_l,
    const float* __restrict__ bes_l,
    __half* __restrict__ out16) {
    const int n = blockIdx.x;
    const int r = blockIdx.y;
    const int* eid = eid_all + (size_t)r * EE;
    const int* off = off_all + (size_t)r * (NN + 1);
    const int* src = src_all + (size_t)r * EE;
    const __half* Xc = go + (size_t)(r * 3 + 0) * NNHH;
    const __half* f = go + (size_t)(r * 3 + 1) * NNHH;
    const __half* Xs = go + (size_t)(r * 3 + 2) * NNHH;
    const float* el = el_all + (size_t)r * NN * NHEADS;
    const float* er = er_all + (size_t)r * NN * NHEADS;
    const float* rdi = rdi_all + (size_t)r * NN;
    const float* bc = bc_l + r * HH;
    const float* gc = gc_l + r * HH;
    const float* bec = bec_l + r * HH;
    const float* bg = bg_l + r * HH;
    const float* gg = gg_l + r * HH;
    const float* beg = beg_l + r * HH;
    const float* bs_ = bs_l + r * HH;
    const float* gs = gs_l + r * HH;
    const float* bes = bes_l + r * HH;

    int p0 = off[n], p1 = off[n + 1];
    int t = threadIdx.x;
    int h = t >> 4;

    __shared__ float sh_m[NHEADS], sh_invs[NHEADS];
    if (t < NHEADS) {
        float ern = er[n * NHEADS + t];
        float mx = -INFINITY;
        for (int p = p0; p < p1; p++) {
            float x = el[src[eid[p]] * NHEADS + t] + ern;
            x = (x > 0.0f) ? x : 0.2f * x;
            mx = fmaxf(mx, x);
        }
        float s = 0.0f;
        for (int p = p0; p < p1; p++) {
            float x = el[src[eid[p]] * NHEADS + t] + ern;
            x = (x > 0.0f) ? x : 0.2f * x;
            s += expf(x - mx);
        }
        sh_m[t] = mx;
        sh_invs[t] = (s > 0.0f) ? (1.0f / s) : 1.0f;
    }
    __syncthreads();

    float mh = sh_m[h];
    float invs = sh_invs[h];
    float ern = er[n * NHEADS + h];

    float4 ac = make_float4(0.f, 0.f, 0.f, 0.f);
    float4 ag = make_float4(0.f, 0.f, 0.f, 0.f);
    for (int p = p0; p < p1; p++) {
        int e = eid[p];
        int sn = src[e];
        float4 rc = load4h(Xc + (size_t)sn * HH, t);
        float4 rg = load4h(f + (size_t)sn * HH, t);
        float x = el[sn * NHEADS + h] + ern;
        x = (x > 0.0f) ? x : 0.2f * x;
        float a = expf(x - mh) * invs;
        ac.x += rc.x; ac.y += rc.y; ac.z += rc.z; ac.w += rc.w;
        ag.x += a * rg.x; ag.y += a * rg.y; ag.z += a * rg.z; ag.w += a * rg.w;
    }

    float sc = rdi[n];
    float4 bb = ((const float4*)bc)[t];
    float4 v = make_float4(ac.x * sc + bb.x, ac.y * sc + bb.y,
                           ac.z * sc + bb.z, ac.w * sc + bb.w);
    float4 y = ln_elu_core4(v, gc, bec);
    float rx = y.x, ry = y.y, rz = y.z, rw = y.w;

    bb = ((const float4*)bg)[t];
    v = make_float4(ag.x + bb.x, ag.y + bb.y, ag.z + bb.z, ag.w + bb.w);
    y = ln_elu_core4(v, gg, beg);
    rx += y.x; ry += y.y; rz += y.z; rw += y.w;

    float4 xs = load4h(Xs + (size_t)n * HH, t);
    bb = ((const float4*)bs_)[t];
    v = make_float4(xs.x + bb.x, xs.y + bb.y, xs.z + bb.z, xs.w + bb.w);
    y = ln_elu_core4(v, gs, bes);
    rx += y.x; ry += y.y; rz += y.z; rw += y.w;

    __half2* op = (__half2*)(out16 + (size_t)n * (RR * HH) + (size_t)r * HH + 4 * t);
    op[0] = __floats2half2_rn(rx, ry);
    op[1] = __floats2half2_rn(rz, rw);
}

// ---------------- GAT attn-score precompute (batched over r) ----------------
__global__ void gat_el_er(const __half* __restrict__ go,
                          const float* __restrict__ al_l,
                          const float* __restrict__ ar_l,
                          float* __restrict__ el_all, float* __restrict__ er_all) {
    int idx = blockIdx.x * blockDim.x + threadIdx.x;
    if (idx >= NN * NHEADS) return;
    int r = blockIdx.y;
    int n = idx >> 3;
    int hh = idx & 7;
    const __half* f = go + (size_t)(r * 3 + 1) * NNHH;
    const __half* fr = f + (size_t)n * HH + hh * DHH;
    const float* a1 = al_l + r * NHEADS * DHH + hh * DHH;
    const float* a2 = ar_l + r * NHEADS * DHH + hh * DHH;
    float s1 = 0.0f, s2 = 0.0f;
#pragma unroll 8
    for (int d = 0; d < DHH; d++) {
        float fv = __half2float(fr[d]);
        s1 += fv * a1[d];
        s2 += fv * a2[d];
    }
    el_all[(size_t)r * NN * NHEADS + idx] = s1;
    er_all[(size_t)r * NN * NHEADS + idx] = s2;
}

// ---------------- relation MHA (3 tokens) + mean ----------------
__global__ __launch_bounds__(256) void mha_mean(
    const __half* __restrict__ q, const __half* __restrict__ k,
    const __half* __restrict__ v, float* __restrict__ out,
    __half* __restrict__ out16) {
    int n = blockIdx.x;
    int hd = threadIdx.x >> 5;
    int lane = threadIdx.x & 31;
    size_t base = (size_t)n * RR * HH + hd * DHH;
    float qa[RR], qb[RR], ka[RR], kb[RR], va[RR], vb[RR];
#pragma unroll
    for (int r = 0; r < RR; r++) {
        size_t off = base + (size_t)r * HH;
        qa[r] = __half2float(q[off + lane]);
        qb[r] = __half2float(q[off + lane + 32]);
        ka[r] = __half2float(k[off + lane]);
        kb[r] = __half2float(k[off + lane + 32]);
        va[r] = __half2float(v[off + lane]);
        vb[r] = __half2float(v[off + lane + 32]);
    }
    float sc[RR][RR];
#pragma unroll
    for (int r = 0; r < RR; r++)
#pragma unroll
        for (int t = 0; t < RR; t++) {
            float p = qa[r] * ka[t] + qb[r] * kb[t];
#pragma unroll
            for (int o = 16; o > 0; o >>= 1) p += __shfl_xor_sync(0xffffffffu, p, o);
            sc[r][t] = p * 0.125f;
        }
    float w0 = 0.0f, w1 = 0.0f, w2 = 0.0f;
#pragma unroll
    for (int r = 0; r < RR; r++) {
        float mx = fmaxf(sc[r][0], fmaxf(sc[r][1], sc[r][2]));
        float e0 = expf(sc[r][0] - mx);
        float e1 = expf(sc[r][1] - mx);
        float e2 = expf(sc[r][2] - mx);
        float inv = 1.0f / (e0 + e1 + e2);
        w0 += e0 * inv;
        w1 += e1 * inv;
        w2 += e2 * inv;
    }
    const float third = 1.0f / 3.0f;
    float oa = (w0 * va[0] + w1 * va[1] + w2 * va[2]) * third;
    float ob = (w0 * vb[0] + w1 * vb[1] + w2 * vb[2]) * third;
    size_t o0 = (size_t)n * HH + hd * DHH + lane;
    out[o0] = oa;
    out[o0 + 32] = ob;
    out16[o0] = __float2half_rn(oa);
    out16[o0 + 32] = __float2half_rn(ob);
}

// ---------------- classifier ----------------
__global__ void classify(const float* __restrict__ h, const float* __restrict__ W,
                         const float* __restrict__ b, float* __restrict__ out) {
    int idx = blockIdx.x * blockDim.x + threadIdx.x;
    if (idx >= NN * NCLSS) return;
    int n = idx / NCLSS;
    int c = idx % NCLSS;
    const float* hr = h + (size_t)n * HH;
    float sum = b[c];
#pragma unroll 8
    for (int j = 0; j < HH; j++) sum += hr[j] * W[j * NCLSS + c];
    out[idx] = sum;
}

// ---------------- launch ----------------
extern "C" void kernel_launch(void* const* d_in, const int* in_sizes, int n_in,
                              void* d_out, int out_size) {
    const float* feature = (const float*)d_in[0];
    const int* src = (const int*)d_in[1];
    const int* dst = (const int*)d_in[2];
    const float* Wc = (const float*)d_in[3];
    const float* bc = (const float*)d_in[4];
    const float* gc = (const float*)d_in[5];
    const float* betac = (const float*)d_in[6];
    const float* Wg = (const float*)d_in[7];
    const float* bg = (const float*)d_in[8];
    const float* al = (const float*)d_in[9];
    const float* ar = (const float*)d_in[10];
    const float* gg = (const float*)d_in[11];
    const float* betag = (const float*)d_in[12];
    const float* Ws = (const float*)d_in[13];
    const float* bs = (const float*)d_in[14];
    const float* gs = (const float*)d_in[15];
    const float* betas = (const float*)d_in[16];
    const float* Wq = (const float*)d_in[17];
    const float* bq = (const float*)d_in[18];
    const float* Wk = (const float*)d_in[19];
    const float* bk = (const float*)d_in[20];
    const float* Wv = (const float*)d_in[21];
    const float* bv = (const float*)d_in[22];
    const float* Wout = (const float*)d_in[23];
    const float* bout = (const float*)d_in[24];
    float* out = (float*)d_out;

    float *p_h, *p_rdo, *p_rdi, *p_el, *p_er;
    __half *p_h16, *p_go16, *p_stk16, *p_w16, *p_q, *p_k, *p_v;
    int *p_cnt, *p_cur, *p_off, *p_eid, *p_psum;
    cudaGetSymbolAddress((void**)&p_h, g_h);
    cudaGetSymbolAddress((void**)&p_h16, g_h16);
    cudaGetSymbolAddress((void**)&p_go16, g_go16);
    cudaGetSymbolAddress((void**)&p_stk16, g_stk16);
    cudaGetSymbolAddress((void**)&p_q, g_q);
    cudaGetSymbolAddress((void**)&p_k, g_k);
    cudaGetSymbolAddress((void**)&p_v, g_v);
    cudaGetSymbolAddress((void**)&p_w16, g_w16);
    cudaGetSymbolAddress((void**)&p_rdo, g_rdo);
    cudaGetSymbolAddress((void**)&p_rdi, g_rdi);
    cudaGetSymbolAddress((void**)&p_el, g_el);
    cudaGetSymbolAddress((void**)&p_er, g_er);
    cudaGetSymbolAddress((void**)&p_cnt, g_cnt);
    cudaGetSymbolAddress((void**)&p_cur, g_cur);
    cudaGetSymbolAddress((void**)&p_off, g_off);
    cudaGetSymbolAddress((void**)&p_eid, g_eid);
    cudaGetSymbolAddress((void**)&p_psum, g_psum);

    cudaFuncSetAttribute(f16gemm9, cudaFuncAttributeMaxDynamicSharedMemorySize,
                         GEMM_SMEM);

    const size_t WHH = (size_t)HH * HH;
    __half* w16_Wc = p_w16;
    __half* w16_Wg = p_w16 + 6 * WHH;
    __half* w16_Ws = p_w16 + 12 * WHH;
    __half* w16_Wq = p_w16 + 18 * WHH;
    __half* w16_Wk = p_w16 + 20 * WHH;
    __half* w16_Wv = p_w16 + 22 * WHH;

    // batched transpose+convert (22 + 2 matrices) + feature cvt
    {
        TP22 tp;
        for (int i = 0; i < 6; i++) {
            tp.in[i] = Wc + (size_t)i * WHH;
            tp.out[i] = w16_Wc + (size_t)i * WHH;
            tp.in[6 + i] = Wg + (size_t)i * WHH;
            tp.out[6 + i] = w16_Wg + (size_t)i * WHH;
            tp.in[12 + i] = Ws + (size_t)i * WHH;
            tp.out[12 + i] = w16_Ws + (size_t)i * WHH;
        }
        for (int i = 0; i < 2; i++) {
            tp.in[18 + i] = Wq + (size_t)i * WHH;
            tp.out[18 + i] = w16_Wq + (size_t)i * WHH;
            tp.in[20 + i] = Wk + (size_t)i * WHH;
            tp.out[20 + i] = w16_Wk + (size_t)i * WHH;
        }
        transpose_cvt16_all<<<dim3(16, 16, 22), dim3(32, 8)>>>(tp);
        TP22 tpv;
        for (int i = 0; i < 2; i++) {
            tpv.in[i] = Wv + (size_t)i * WHH;
            tpv.out[i] = w16_Wv + (size_t)i * WHH;
        }
        transpose_cvt16_all<<<dim3(16, 16, 2), dim3(32, 8)>>>(tpv);
        int n4f = (int)(NNHH / 4);
        cvt_f16_vec<<<(n4f + 255) / 256, 256>>>((const float4*)feature,
                                                (__half2*)p_h16, n4f);
    }

    cudaMemsetAsync(p_rdo, 0, (size_t)RR * NN * sizeof(float), 0);
    cudaMemsetAsync(p_rdi, 0, (size_t)RR * NN * sizeof(float), 0);
    cudaMemsetAsync(p_cnt, 0, (size_t)RR * NN * sizeof(int), 0);
    cudaMemsetAsync(p_cur, 0, (size_t)RR * NN * sizeof(int), 0);
    degree_count<<<(RR * EE + 255) / 256, 256>>>(src, dst, p_rdo, p_rdi, p_cnt);
    degree_finalize2<<<(RR * NN + 255) / 256, 256>>>(p_rdo, p_rdi, RR * NN);
    scan_partial<<<RR * NCH, 1024>>>(p_cnt, p_off, p_psum);
    scan_mid<<<RR, 32>>>(p_psum, p_off);
    scan_apply<<<RR * NCH, 1024>>>(p_off, p_psum);
    build_adj<<<(RR * EE + 255) / 256, 256>>>(dst, p_off, p_cur, p_eid);

    const dim3 gemm_grid_n(4, (NN + 127) / 128, 9);
    const dim3 gemm_grid_nr(4, (NN * RR + 127) / 128, 3);
    const dim3 elgrid((NN * NHEADS + 255) / 256, 3);
    const dim3 fgrid(NN, 3);

    for (int l = 0; l < LL; l++) {
        const size_t lbase = (size_t)l * RR;

        G9 a9;
        for (int r = 0; r < RR; r++) {
            const size_t lr = lbase + r;
            a9.W[r * 3 + 0] = w16_Wc + lr * WHH;
            a9.W[r * 3 + 1] = w16_Wg + lr * WHH;
            a9.W[r * 3 + 2] = w16_Ws + lr * WHH;
            for (int bI = 0; bI < 3; bI++) {
                a9.C[r * 3 + bI] = p_go16 + (size_t)(r * 3 + bI) * NNHH;
                a9.b[r * 3 + bI] = nullptr;
            }
            a9.rs[r * 3 + 0] = p_rdo + (size_t)r * NN;
            a9.rs[r * 3 + 1] = nullptr;
            a9.rs[r * 3 + 2] = nullptr;
        }
        f16gemm9<<<gemm_grid_n, 256, GEMM_SMEM>>>(p_h16, a9, NN);

        gat_el_er<<<elgrid, 256>>>(p_go16, al + lbase * NHEADS * DHH,
                                   ar + lbase * NHEADS * DHH, p_el, p_er);
        fused_branches<<<fgrid, 128>>>(
            p_eid, p_off, src, p_go16, p_el, p_er, p_rdi,
            bc + lbase * HH, gc + lbase * HH, betac + lbase * HH,
            bg + lbase * HH, gg + lbase * HH, betag + lbase * HH,
            bs + lbase * HH, gs + lbase * HH, betas + lbase * HH,
            p_stk16);

        G9 aq;
        aq.W[0] = w16_Wq + (size_t)l * WHH;
        aq.W[1] = w16_Wk + (size_t)l * WHH;
        aq.W[2] = w16_Wv + (size_t)l * WHH;
        aq.C[0] = p_q;
        aq.C[1] = p_k;
        aq.C[2] = p_v;
        aq.rs[0] = nullptr; aq.rs[1] = nullptr; aq.rs[2] = nullptr;
        aq.b[0] = bq + (size_t)l * HH;
        aq.b[1] = bk + (size_t)l * HH;
        aq.b[2] = bv + (size_t)l * HH;
        for (int zz = 3; zz < 9; zz++) {
            aq.W[zz] = nullptr; aq.C[zz] = nullptr;
            aq.rs[zz] = nullptr; aq.b[zz] = nullptr;
        }
        f16gemm9<<<gemm_grid_nr, 256, GEMM_SMEM>>>(p_stk16, aq, NN * RR);

        mha_mean<<<NN, 256>>>(p_q, p_k, p_v, p_h, p_h16);
    }

    classify<<<(NN * NCLSS + 255) / 256, 256>>>(p_h, Wout, bout, out);
}